// round 3
// baseline (speedup 1.0000x reference)
#include <cuda_runtime.h>

// Shapes fixed by the problem
#define B_  32
#define Q_  900
#define C_  91
#define T_  30
#define BQ  (B_ * Q_)
#define CSZ ((size_t)B_ * Q_ * Q_)   // 25,920,000
#define NF4 (Q_ / 4)                 // 225 float4 columns per row

// Scratch (device globals — no allocation allowed)
__device__ int           g_label[BQ];
__device__ unsigned char g_mask[BQ];

// ---------------------------------------------------------------------------
__device__ __forceinline__ float fast_rcp(float x) {
    float y = __int_as_float(0x7EF311C3 - __float_as_int(x));
    y = y * fmaf(-x, y, 2.0f);
    y = y * fmaf(-x, y, 2.0f);
    return y;
}

__device__ __forceinline__ float4 to_xyxy(float4 b) {
    float hw = 0.5f * b.z, hh = 0.5f * b.w;
    return make_float4(b.x - hw, b.y - hh, b.x + hw, b.y + hh);
}

__device__ __forceinline__ float giou(float4 xa, float aa, float4 xb, float ab) {
    float w = fmaxf(fminf(xa.z, xb.z) - fmaxf(xa.x, xb.x), 0.0f);
    float h = fmaxf(fminf(xa.w, xb.w) - fmaxf(xa.y, xb.y), 0.0f);
    float inter = w * h;
    float uni = aa + ab - inter;
    float wc = fmaxf(fmaxf(xa.z, xb.z) - fminf(xa.x, xb.x), 0.0f);
    float hc = fmaxf(fmaxf(xa.w, xb.w) - fminf(xa.y, xb.y), 0.0f);
    float ac = wc * hc;
    return inter * fast_rcp(uni) - (ac - uni) * fast_rcp(ac);
}

// order-preserving float->uint mapping (for integer max-reduce)
__device__ __forceinline__ unsigned ordkey(float v) {
    unsigned u = __float_as_uint(v);
    return ((int)u >= 0) ? (u | 0x80000000u) : ~u;
}

// ---------------------------------------------------------------------------
// Kernel A: pseudo-label generation. One warp per (b, j_base).
//   argmax over 91 logits via REDUX.MAX on ordered keys + ballots for index.
//   keep_prob: sigmoid(max)>0.5  <=>  max>0.
// ---------------------------------------------------------------------------
__global__ __launch_bounds__(256) void pseudo_kernel(
    const float*  __restrict__ logits_base,
    const float4* __restrict__ boxes_base,
    const float4* __restrict__ targets,
    float* __restrict__ mask_out, int write_mask)
{
    int w    = (blockIdx.x * blockDim.x + threadIdx.x) >> 5;
    int lane = threadIdx.x & 31;
    if (w >= BQ) return;
    int b = w / Q_;

    const float* lg = logits_base + (size_t)w * C_;
    float v0 = lg[lane];
    float v1 = lg[lane + 32];
    float v2 = (lane + 64 < C_) ? lg[lane + 64] : -3.4e38f;
    unsigned k0 = ordkey(v0), k1 = ordkey(v1), k2 = ordkey(v2);
    unsigned km = max(k0, max(k1, k2));
    unsigned best = __reduce_max_sync(0xffffffffu, km);

    // first-occurrence argmax index
    int bi;
    unsigned m0 = __ballot_sync(0xffffffffu, k0 == best);
    unsigned m1 = __ballot_sync(0xffffffffu, k1 == best);
    unsigned m2 = __ballot_sync(0xffffffffu, k2 == best);
    if (m0)      bi = __ffs(m0) - 1;
    else if (m1) bi = 32 + __ffs(m1) - 1;
    else         bi = 64 + __ffs(m2) - 1;

    bool keep_prob = best > 0x80000000u;   // max logit > 0  <=> sigmoid > 0.5

    float4 bb = boxes_base[w];
    float4 xb = to_xyxy(bb);
    float  ab = (xb.z - xb.x) * (xb.w - xb.y);

    bool ok = true;
    if (lane < T_) {
        float4 tb = targets[b * T_ + lane];
        float4 xt = to_xyxy(tb);
        float  at = (xt.z - xt.x) * (xt.w - xt.y);
        float  g  = giou(xb, ab, xt, at);
        ok = ((-g) > -0.1f);
    }
    bool all_ok = __all_sync(0xffffffffu, ok);

    if (lane == 0) {
        unsigned char m = (keep_prob && all_ok) ? 1 : 0;
        g_label[w] = bi;
        g_mask[w]  = m;
        if (write_mask) mask_out[w] = (float)m;
    }
}

// ---------------------------------------------------------------------------
// Kernel C: main 900x900 cost matrix, sparsity-aware.
//   Block = (32,8) threads. Tile: 128 j (4 per thread, float4 stores) x 16 i.
//   Fast path: no valid pseudo target in j-tile -> pure 1e9 float4 fill.
//   Slow path (rare): compute focal class cost from raw logits + L1 + GIoU.
// ---------------------------------------------------------------------------
__global__ __launch_bounds__(256) void cost_kernel(
    const float*  __restrict__ logits,      // current pred logits [B,Q,C]
    const float4* __restrict__ boxes,       // current pred boxes
    const float4* __restrict__ boxes_base,  // pseudo-target boxes
    float* __restrict__ out)
{
    __shared__ float4 sjb[128], sjx[128];
    __shared__ float  sja[128];
    __shared__ int    sjl[128];
    __shared__ unsigned char sjm[128];
    __shared__ float4 sib[16], six[16];
    __shared__ float  sia[16];
    __shared__ int    s_any;

    int b  = blockIdx.z;
    int j0 = blockIdx.x * 128;
    int i0 = blockIdx.y * 16;
    int tx = threadIdx.x, ty = threadIdx.y;
    int tid = ty * 32 + tx;

    if (tid == 0) s_any = 0;
    __syncthreads();

    if (tid < 128) {
        int j  = j0 + tid;
        unsigned char m = 0;
        if (j < Q_) {
            m = g_mask[b * Q_ + j];
            float4 bb = boxes_base[b * Q_ + j];
            float4 xb = to_xyxy(bb);
            sjb[tid] = bb;
            sjx[tid] = xb;
            sja[tid] = (xb.z - xb.x) * (xb.w - xb.y);
            sjl[tid] = g_label[b * Q_ + j];
        }
        sjm[tid] = m;
        if (m) atomicOr(&s_any, 1);
    } else if (tid < 144) {
        int ii = tid - 128;
        int i  = i0 + ii;
        int ic = (i < Q_) ? i : (Q_ - 1);
        float4 bb = boxes[b * Q_ + ic];
        float4 xb = to_xyxy(bb);
        sib[ii] = bb;
        six[ii] = xb;
        sia[ii] = (xb.z - xb.x) * (xb.w - xb.y);
    }
    __syncthreads();

    int col = blockIdx.x * 32 + tx;          // float4 column index
    if (col >= NF4) return;
    float4* out4 = (float4*)out;
    size_t  obase = ((size_t)b * Q_ + i0) * NF4 + col;
    const float4 FILL = make_float4(1e9f, 1e9f, 1e9f, 1e9f);

    if (!s_any) {
        // ---- fast path: pure fill ----
        #pragma unroll
        for (int k = 0; k < 2; ++k) {
            int ii = ty * 2 + k;
            if (i0 + ii < Q_)
                out4[obase + (size_t)ii * NF4] = FILL;
        }
        return;
    }

    // ---- slow path (rare): per-lane compute where masked-in ----
    int jl = tx * 4;                          // local j base in tile
    unsigned char m4[4]; int lab[4];
    float4 bj[4], xj[4]; float aj[4];
    #pragma unroll
    for (int c = 0; c < 4; ++c) {
        m4[c]  = sjm[jl + c];
        lab[c] = sjl[jl + c];
        bj[c]  = sjb[jl + c];
        xj[c]  = sjx[jl + c];
        aj[c]  = sja[jl + c];
    }

    #pragma unroll
    for (int k = 0; k < 2; ++k) {
        int ii = ty * 2 + k;
        int i  = i0 + ii;
        if (i >= Q_) break;
        float4 bi = sib[ii], xi = six[ii];
        float  ai = sia[ii];
        const float* lrow = logits + (size_t)(b * Q_ + i) * C_;

        float4 r = FILL;
        float* rp = &r.x;
        #pragma unroll
        for (int c = 0; c < 4; ++c) {
            if (m4[c]) {
                float x   = __ldg(lrow + lab[c]);
                float t   = __expf(-x);
                float p   = fast_rcp(1.0f + t);
                float omp = 1.0f - p;
                float pos = 0.25f * omp * omp * (-__logf(p   + 1e-8f));
                float neg = 0.75f * p   * p   * (-__logf(omp + 1e-8f));
                float cls = 2.0f * (pos - neg);
                float l1  = fabsf(bi.x - bj[c].x) + fabsf(bi.y - bj[c].y)
                          + fabsf(bi.z - bj[c].z) + fabsf(bi.w - bj[c].w);
                float g   = giou(xi, ai, xj[c], aj[c]);
                rp[c] = fmaf(5.0f, l1, cls) - 2.0f * g;
            }
        }
        out4[obase + (size_t)ii * NF4] = r;
    }
}

// ---------------------------------------------------------------------------
extern "C" void kernel_launch(void* const* d_in, const int* in_sizes, int n_in,
                              void* d_out, int out_size)
{
    const float*  pred_logits      = (const float*) d_in[0];
    const float4* pred_boxes       = (const float4*)d_in[1];
    const float*  pred_logits_base = (const float*) d_in[2];
    const float4* pred_boxes_base  = (const float4*)d_in[3];
    const float4* targets_boxes    = (const float4*)d_in[4];
    float* out = (float*)d_out;

    int write_mask = (out_size >= (int)(CSZ + BQ)) ? 1 : 0;

    pseudo_kernel<<<(BQ + 7) / 8, 256>>>(pred_logits_base, pred_boxes_base,
                                         targets_boxes, out + CSZ, write_mask);

    dim3 grid(8, 57, B_), block(32, 8);
    cost_kernel<<<grid, block>>>(pred_logits, pred_boxes, pred_boxes_base, out);
}

// round 4
// speedup vs baseline: 1.1131x; 1.1131x over previous
#include <cuda_runtime.h>

// Shapes fixed by the problem
#define B_  32
#define Q_  900
#define C_  91
#define T_  30
#define BQ  (B_ * Q_)                 // 28800
#define CSZ ((size_t)B_ * Q_ * Q_)    // 25,920,000
#define N4  (CSZ / 4)                 // 6,480,000 float4s
#define FILL_BLOCKS 2048
#define PSEUDO_BLOCKS (BQ / 8)        // 3600 (8 warps/block, warp per row)

// Scratch (device globals — no allocation allowed)
__device__ int           g_label[BQ];
__device__ unsigned char g_mask[BQ];

// ---------------------------------------------------------------------------
__device__ __forceinline__ float4 to_xyxy(float4 b) {
    float hw = 0.5f * b.z, hh = 0.5f * b.w;
    return make_float4(b.x - hw, b.y - hh, b.x + hw, b.y + hh);
}

// Precise GIoU (IEEE divisions) — matches reference semantics closely; used in
// both the boundary-sensitive filter and the (rare) computed columns.
__device__ __forceinline__ float giou_precise(float4 xa, float aa, float4 xb, float ab) {
    float w = fmaxf(fminf(xa.z, xb.z) - fmaxf(xa.x, xb.x), 0.0f);
    float h = fmaxf(fminf(xa.w, xb.w) - fmaxf(xa.y, xb.y), 0.0f);
    float inter = w * h;
    float uni = aa + ab - inter;
    float wc = fmaxf(fmaxf(xa.z, xb.z) - fminf(xa.x, xb.x), 0.0f);
    float hc = fmaxf(fmaxf(xa.w, xb.w) - fminf(xa.y, xb.y), 0.0f);
    float ac = wc * hc;
    return inter / uni - (ac - uni) / ac;
}

__device__ __forceinline__ unsigned ordkey(float v) {
    unsigned u = __float_as_uint(v);
    return ((int)u >= 0) ? (u | 0x80000000u) : ~u;
}

// ---------------------------------------------------------------------------
// K1: fused fill + pseudo-label generation.
//   Blocks [0, FILL_BLOCKS): grid-stride float4 fill of C with 1e9.
//   Blocks [FILL_BLOCKS, +PSEUDO_BLOCKS): warp per (b,q_base):
//     REDUX argmax over 91 logits; keep_prob = max logit > 0;
//     keep_giou = all 30 targets have giou < 0.1 (precise arithmetic).
// ---------------------------------------------------------------------------
__global__ __launch_bounds__(256) void k1_fill_pseudo(
    const float*  __restrict__ logits_base,
    const float4* __restrict__ boxes_base,
    const float4* __restrict__ targets,
    float* __restrict__ out, int write_mask)
{
    int bx = blockIdx.x;
    if (bx < FILL_BLOCKS) {
        float4* o4 = (float4*)out;
        const float4 F = make_float4(1e9f, 1e9f, 1e9f, 1e9f);
        for (size_t idx = (size_t)bx * 256 + threadIdx.x; idx < N4;
             idx += (size_t)FILL_BLOCKS * 256)
            o4[idx] = F;
        return;
    }

    int w    = ((bx - FILL_BLOCKS) * 256 + threadIdx.x) >> 5;  // exactly covers BQ
    int lane = threadIdx.x & 31;
    int b    = w / Q_;

    const float* lg = logits_base + (size_t)w * C_;
    float v0 = lg[lane];
    float v1 = lg[lane + 32];
    float v2 = (lane + 64 < C_) ? lg[lane + 64] : -3.4e38f;
    unsigned k0 = ordkey(v0), k1 = ordkey(v1), k2 = ordkey(v2);
    unsigned best = __reduce_max_sync(0xffffffffu, max(k0, max(k1, k2)));

    int bi;
    unsigned m0 = __ballot_sync(0xffffffffu, k0 == best);
    unsigned m1 = __ballot_sync(0xffffffffu, k1 == best);
    unsigned m2 = __ballot_sync(0xffffffffu, k2 == best);
    if (m0)      bi = __ffs(m0) - 1;
    else if (m1) bi = 32 + __ffs(m1) - 1;
    else         bi = 64 + __ffs(m2) - 1;

    bool keep_prob = best > 0x80000000u;   // max logit > 0 <=> sigmoid > 0.5

    float4 bb = boxes_base[w];
    float4 xb = to_xyxy(bb);
    float  ab = (xb.z - xb.x) * (xb.w - xb.y);

    bool ok = true;
    if (lane < T_) {
        float4 tb = targets[b * T_ + lane];
        float4 xt = to_xyxy(tb);
        float  at = (xt.z - xt.x) * (xt.w - xt.y);
        float  g  = giou_precise(xb, ab, xt, at);
        ok = ((-g) > -0.1f);
    }
    bool all_ok = __all_sync(0xffffffffu, ok);

    if (lane == 0) {
        unsigned char m = (keep_prob && all_ok) ? 1 : 0;
        g_label[w] = bi;
        g_mask[w]  = m;
        if (write_mask) out[CSZ + w] = (float)m;
    }
}

// ---------------------------------------------------------------------------
// K2: compute only the valid pseudo-target columns (V expected ~0).
//   256 blocks. Each block: parallel-stage its 113 candidate mask bytes
//   (thread t checks w = blockIdx.x + 256*t), collect valid w's in smem,
//   then all 256 threads cooperate per valid column (thread = i index).
// ---------------------------------------------------------------------------
__global__ __launch_bounds__(256) void k2_columns(
    const float*  __restrict__ logits,       // current pred logits [B,Q,C]
    const float4* __restrict__ boxes,        // current pred boxes
    const float4* __restrict__ boxes_base,   // pseudo-target boxes
    float* __restrict__ out)
{
    __shared__ int s_valid[128];
    __shared__ int s_n;
    int t = threadIdx.x;
    if (t == 0) s_n = 0;
    __syncthreads();

    int w = blockIdx.x + 256 * t;            // candidates: w ≡ blockIdx.x (mod 256)
    if (w < BQ && g_mask[w]) {
        int slot = atomicAdd(&s_n, 1);
        s_valid[slot] = w;
    }
    __syncthreads();

    int n = s_n;
    for (int v = 0; v < n; ++v) {
        int wj  = s_valid[v];
        int b   = wj / Q_;
        int j   = wj - b * Q_;
        int lab = g_label[wj];

        float4 bj = boxes_base[wj];
        float4 xj = to_xyxy(bj);
        float  aj = (xj.z - xj.x) * (xj.w - xj.y);

        for (int i = t; i < Q_; i += 256) {
            float4 bi = boxes[b * Q_ + i];
            float4 xi = to_xyxy(bi);
            float  ai = (xi.z - xi.x) * (xi.w - xi.y);

            // focal class cost at label lab, weighted by W_CLASS=2
            float x   = logits[((size_t)b * Q_ + i) * C_ + lab];
            float p   = 1.0f / (1.0f + __expf(-x));
            float omp = 1.0f - p;
            float pos = 0.25f * omp * omp * (-__logf(p   + 1e-8f));
            float neg = 0.75f * p   * p   * (-__logf(omp + 1e-8f));
            float cls = 2.0f * (pos - neg);

            float l1 = fabsf(bi.x - bj.x) + fabsf(bi.y - bj.y)
                     + fabsf(bi.z - bj.z) + fabsf(bi.w - bj.w);
            float g  = giou_precise(xi, ai, xj, aj);

            out[((size_t)b * Q_ + i) * Q_ + j] = fmaf(5.0f, l1, cls) - 2.0f * g;
        }
    }
}

// ---------------------------------------------------------------------------
extern "C" void kernel_launch(void* const* d_in, const int* in_sizes, int n_in,
                              void* d_out, int out_size)
{
    const float*  pred_logits      = (const float*) d_in[0];
    const float4* pred_boxes       = (const float4*)d_in[1];
    const float*  pred_logits_base = (const float*) d_in[2];
    const float4* pred_boxes_base  = (const float4*)d_in[3];
    const float4* targets_boxes    = (const float4*)d_in[4];
    float* out = (float*)d_out;

    int write_mask = (out_size >= (int)(CSZ + BQ)) ? 1 : 0;

    k1_fill_pseudo<<<FILL_BLOCKS + PSEUDO_BLOCKS, 256>>>(
        pred_logits_base, pred_boxes_base, targets_boxes, out, write_mask);

    k2_columns<<<256, 256>>>(pred_logits, pred_boxes, pred_boxes_base, out);
}

// round 5
// speedup vs baseline: 2.5328x; 2.2755x over previous
#include <cuda_runtime.h>

// Shapes fixed by the problem
#define B_  32
#define Q_  900
#define C_  91
#define T_  30
#define BQ  (B_ * Q_)                 // 28800
#define CSZ ((size_t)B_ * Q_ * Q_)    // 25,920,000
#define NR4 (Q_ / 4)                  // 225 float4 per row
#define ROWS_PER_BLK 8

// Scratch (device globals — no allocation allowed)
__device__ int g_cnt[B_];     // valid pseudo-target count per batch
__device__ int g_vjl[BQ];     // per batch: packed (j | label<<16), compacted

// ---------------------------------------------------------------------------
__device__ __forceinline__ float fast_rcp(float x) {
    float y = __int_as_float(0x7EF311C3 - __float_as_int(x));
    y = y * fmaf(-x, y, 2.0f);
    y = y * fmaf(-x, y, 2.0f);
    return y;
}

__device__ __forceinline__ float4 to_xyxy(float4 b) {
    float hw = 0.5f * b.z, hh = 0.5f * b.w;
    return make_float4(b.x - hw, b.y - hh, b.x + hw, b.y + hh);
}

// Precise GIoU (IEEE div) — used only in the boundary-sensitive filter.
__device__ __forceinline__ float giou_precise(float4 xa, float aa, float4 xb, float ab) {
    float w = fmaxf(fminf(xa.z, xb.z) - fmaxf(xa.x, xb.x), 0.0f);
    float h = fmaxf(fminf(xa.w, xb.w) - fmaxf(xa.y, xb.y), 0.0f);
    float inter = w * h;
    float uni = aa + ab - inter;
    float wc = fmaxf(fmaxf(xa.z, xb.z) - fminf(xa.x, xb.x), 0.0f);
    float hc = fmaxf(fmaxf(xa.w, xb.w) - fminf(xa.y, xb.y), 0.0f);
    float ac = wc * hc;
    return inter / uni - (ac - uni) / ac;
}

// Fast GIoU for cost entries: single fused reciprocal (FMA pipe only).
// giou = inter/uni - (ac-uni)/ac = (inter*ac - (ac-uni)*uni) / (uni*ac)
__device__ __forceinline__ float giou_fast(float4 xa, float aa, float4 xb, float ab) {
    float w = fmaxf(fminf(xa.z, xb.z) - fmaxf(xa.x, xb.x), 0.0f);
    float h = fmaxf(fminf(xa.w, xb.w) - fmaxf(xa.y, xb.y), 0.0f);
    float inter = w * h;
    float uni = aa + ab - inter;
    float wc = fmaxf(xa.z, xb.z) - fminf(xa.x, xb.x);   // >= 0 by construction
    float hc = fmaxf(xa.w, xb.w) - fminf(xa.y, xb.y);
    float ac = wc * hc;
    float num = inter * ac - (ac - uni) * uni;
    return num * fast_rcp(uni * ac);
}

__device__ __forceinline__ unsigned ordkey(float v) {
    unsigned u = __float_as_uint(v);
    return ((int)u >= 0) ? (u | 0x80000000u) : ~u;
}

// ---------------------------------------------------------------------------
// K0: zero the per-batch counters.
// ---------------------------------------------------------------------------
__global__ void zero_kernel() {
    if (threadIdx.x < B_) g_cnt[threadIdx.x] = 0;
}

// ---------------------------------------------------------------------------
// K1: pseudo-label generation + compaction. One warp per (b, j).
//   argmax via REDUX on ordered keys; keep_prob = max logit > 0;
//   keep_giou = all 30 targets have giou < 0.1 (precise arithmetic).
//   Valid j's appended to g_vjl[b] (order-independent output => deterministic).
// ---------------------------------------------------------------------------
__global__ __launch_bounds__(256) void pseudo_kernel(
    const float*  __restrict__ logits_base,
    const float4* __restrict__ boxes_base,
    const float4* __restrict__ targets,
    float* __restrict__ out, int write_mask)
{
    int w    = (blockIdx.x * 256 + threadIdx.x) >> 5;   // exactly covers BQ
    int lane = threadIdx.x & 31;
    int b    = w / Q_;

    const float* lg = logits_base + (size_t)w * C_;
    float v0 = lg[lane];
    float v1 = lg[lane + 32];
    float v2 = (lane + 64 < C_) ? lg[lane + 64] : -3.4e38f;
    unsigned k0 = ordkey(v0), k1 = ordkey(v1), k2 = ordkey(v2);
    unsigned best = __reduce_max_sync(0xffffffffu, max(k0, max(k1, k2)));

    int bi;
    unsigned m0 = __ballot_sync(0xffffffffu, k0 == best);
    unsigned m1 = __ballot_sync(0xffffffffu, k1 == best);
    unsigned m2 = __ballot_sync(0xffffffffu, k2 == best);
    if (m0)      bi = __ffs(m0) - 1;
    else if (m1) bi = 32 + __ffs(m1) - 1;
    else         bi = 64 + __ffs(m2) - 1;

    bool keep_prob = best > 0x80000000u;   // max logit > 0 <=> sigmoid > 0.5

    float4 bb = boxes_base[w];
    float4 xb = to_xyxy(bb);
    float  ab = (xb.z - xb.x) * (xb.w - xb.y);

    bool ok = true;
    if (lane < T_) {
        float4 tb = targets[b * T_ + lane];
        float4 xt = to_xyxy(tb);
        float  at = (xt.z - xt.x) * (xt.w - xt.y);
        float  g  = giou_precise(xb, ab, xt, at);
        ok = ((-g) > -0.1f);
    }
    bool all_ok = __all_sync(0xffffffffu, ok);

    if (lane == 0) {
        bool m = keep_prob && all_ok;
        if (write_mask) out[CSZ + w] = m ? 1.0f : 0.0f;
        if (m) {
            int slot = atomicAdd(&g_cnt[b], 1);
            g_vjl[b * Q_ + slot] = (w - b * Q_) | (bi << 16);
        }
    }
}

// ---------------------------------------------------------------------------
// K2: main kernel. Block owns 8 rows of batch b.
//   Phase 1: dense float4 fill of its rows with 1e9.
//   Phase 2: scatter-compute the (rare) valid columns into those rows.
//   Lines stay in L2 between phases (same block) -> ~one DRAM write per line.
// ---------------------------------------------------------------------------
__global__ __launch_bounds__(256) void cost_kernel(
    const float*  __restrict__ logits,       // current pred logits [B,Q,C]
    const float4* __restrict__ boxes,        // current pred boxes
    const float4* __restrict__ boxes_base,   // pseudo-target boxes
    float* __restrict__ out)
{
    int b  = blockIdx.y;
    int i0 = blockIdx.x * ROWS_PER_BLK;
    int t  = threadIdx.x;

    // ---- phase 1: dense fill ----
    float4* out4 = (float4*)out;
    const float4 F = make_float4(1e9f, 1e9f, 1e9f, 1e9f);
    #pragma unroll
    for (int k = 0; k < (ROWS_PER_BLK * NR4 + 255) / 256; ++k) {
        int idx = k * 256 + t;
        if (idx < ROWS_PER_BLK * NR4) {
            int i = i0 + idx / NR4;
            if (i < Q_)
                out4[((size_t)b * Q_ + i) * NR4 + idx % NR4] = F;
        }
    }
    __syncthreads();   // order phase-1 global writes before phase-2 overwrites

    // ---- phase 2: compute valid columns only ----
    int n = g_cnt[b];
    int total = ROWS_PER_BLK * n;
    for (int idx = t; idx < total; idx += 256) {
        int i = i0 + idx / n;
        int v = idx - (idx / n) * n;
        if (i >= Q_) break;

        int jl  = g_vjl[b * Q_ + v];
        int j   = jl & 0xFFFF;
        int lab = jl >> 16;

        float4 bi = boxes[b * Q_ + i];
        float4 xi = to_xyxy(bi);
        float  ai = (xi.z - xi.x) * (xi.w - xi.y);

        float4 bj = boxes_base[b * Q_ + j];
        float4 xj = to_xyxy(bj);
        float  aj = (xj.z - xj.x) * (xj.w - xj.y);

        // focal class cost at label lab, weighted by W_CLASS=2
        float x   = logits[((size_t)b * Q_ + i) * C_ + lab];
        float p   = fast_rcp(1.0f + __expf(-x));
        float omp = 1.0f - p;
        float pos = 0.25f * omp * omp * (-__logf(p   + 1e-8f));
        float neg = 0.75f * p   * p   * (-__logf(omp + 1e-8f));
        float cls = 2.0f * (pos - neg);

        float l1 = fabsf(bi.x - bj.x) + fabsf(bi.y - bj.y)
                 + fabsf(bi.z - bj.z) + fabsf(bi.w - bj.w);
        float g  = giou_fast(xi, ai, xj, aj);

        out[((size_t)b * Q_ + i) * Q_ + j] = fmaf(5.0f, l1, cls) - 2.0f * g;
    }
}

// ---------------------------------------------------------------------------
extern "C" void kernel_launch(void* const* d_in, const int* in_sizes, int n_in,
                              void* d_out, int out_size)
{
    const float*  pred_logits      = (const float*) d_in[0];
    const float4* pred_boxes       = (const float4*)d_in[1];
    const float*  pred_logits_base = (const float*) d_in[2];
    const float4* pred_boxes_base  = (const float4*)d_in[3];
    const float4* targets_boxes    = (const float4*)d_in[4];
    float* out = (float*)d_out;

    int write_mask = (out_size >= (int)(CSZ + BQ)) ? 1 : 0;

    zero_kernel<<<1, 32>>>();

    pseudo_kernel<<<BQ / 8, 256>>>(pred_logits_base, pred_boxes_base,
                                   targets_boxes, out, write_mask);

    dim3 grid((Q_ + ROWS_PER_BLK - 1) / ROWS_PER_BLK, B_);  // (113, 32)
    cost_kernel<<<grid, 256>>>(pred_logits, pred_boxes, pred_boxes_base, out);
}